// round 7
// baseline (speedup 1.0000x reference)
#include <cuda_runtime.h>
#include <cuda.h>
#include <cuda_bf16.h>
#include <cstdint>

static constexpr int ENC_DIM = 640;
static constexpr int INNER   = 512;
static constexpr int VOCAB   = 2048;
static constexpr int BT      = 1024;
static constexpr int MROWS   = 65536;

__device__ float g_P[BT * INNER];     // enc_proj + b1
__device__ float g_Q[256 * INNER];    // dec_proj
__device__ float g_W2r[VOCAB * INNER];

#if !defined(__CUDA_ARCH__) || defined(__CUDA_ARCH_FEAT_SM103_ALL) || defined(__CUDA_ARCH_FEAT_SM100_ALL) || defined(__CUDA_ARCH_FEAT_SM101_ALL)
#define HAS_TCGEN05 1
#else
#define HAS_TCGEN05 0
#endif

__device__ __forceinline__ uint32_t smem_to_u32(const void* ptr) {
    uint32_t a;
    asm("{ .reg .u64 t; cvta.to.shared.u64 t, %1; cvt.u32.u64 %0, t; }" : "=r"(a) : "l"(ptr));
    return a;
}
__device__ __forceinline__ float to_tf32(float x) {
    uint32_t u = __float_as_uint(x);
    u = (u + 0x1000u) & 0xFFFFE000u;
    return __uint_as_float(u);
}
__device__ __forceinline__ float tanh_fast(float x) {
    float y;
    asm("tanh.approx.f32 %0, %1;" : "=f"(y) : "f"(x));
    return y;
}

#if HAS_TCGEN05
__device__ __forceinline__ uint32_t elect_one_pred() {
    uint32_t p;
    asm volatile("{\n\t.reg .pred p;\n\telect.sync _|p, 0xFFFFFFFF;\n\tselp.b32 %0, 1, 0, p;\n\t}" : "=r"(p));
    return p;
}
__device__ __forceinline__ uint32_t cluster_ctarank() {
    uint32_t r;
    asm("mov.u32 %0, %%cluster_ctarank;" : "=r"(r));
    return r;
}
#define MBARRIER_INIT(m, c) \
    asm volatile("mbarrier.init.shared.b64 [%0], %1;" :: "r"((uint32_t)(m)), "r"((uint32_t)(c)) : "memory")
#define MBARRIER_EXPECT_TX(m, b) \
    asm volatile("mbarrier.arrive.expect_tx.shared.b64 _, [%0], %1;" :: "r"((uint32_t)(m)), "r"((uint32_t)(b)) : "memory")
// arrive on the LEADER CTA's barrier at same offset (clear bit 24)
#define MBARRIER_ARRIVE_LEADER(m) \
    asm volatile("{\n\t.reg .b32 a;\n\tand.b32 a, %0, 0xFEFFFFFF;\n\tmbarrier.arrive.shared::cluster.b64 _, [a];\n\t}" \
        :: "r"((uint32_t)(m)) : "memory")

#define MBAR_WAIT(m, ph, SEM) do { \
    uint32_t _m = (uint32_t)(m); uint32_t _p = (uint32_t)(ph); uint32_t _d; \
    asm volatile("{\n\t.reg .pred p;\n\tmbarrier.try_wait.parity." SEM ".cta.shared::cta.b64 p, [%1], %2;\n\tselp.b32 %0, 1, 0, p;\n\t}" \
        : "=r"(_d) : "r"(_m), "r"(_p) : "memory"); \
    if (!_d) { \
        asm volatile("{\n\t.reg .pred P1;\n\tWL_%=:\n\tmbarrier.try_wait.parity." SEM ".cta.shared::cta.b64 P1, [%0], %1, 0x989680;\n\t@P1 bra.uni WD_%=;\n\tbra.uni WL_%=;\n\tWD_%=:\n\t}" \
            :: "r"(_m), "r"(_p) : "memory"); \
    } } while(0)
#define MBARRIER_WAIT_PARITY(m, p)          MBAR_WAIT(m, p, "acquire")
#define MBARRIER_WAIT_PARITY_RELAXED(m, p)  MBAR_WAIT(m, p, "relaxed")

#define TCGEN05_ALLOC_CG2(sa, n) \
    asm volatile("tcgen05.alloc.cta_group::2.sync.aligned.shared::cta.b32 [%0], %1;" :: "r"((uint32_t)(sa)), "r"((uint32_t)(n)) : "memory")
#define TCGEN05_DEALLOC_CG2(t, n) \
    asm volatile("tcgen05.dealloc.cta_group::2.sync.aligned.b32 %0, %1;" :: "r"(t), "r"((uint32_t)(n)))
#define TCGEN05_RELINQ_CG2() \
    asm volatile("tcgen05.relinquish_alloc_permit.cta_group::2.sync.aligned;")
#define TCGEN05_COMMIT_MC_CG2(m, mask) \
    asm volatile("tcgen05.commit.cta_group::2.mbarrier::arrive::one.shared::cluster.multicast::cluster.b64 [%0], %1;" \
        :: "r"((uint32_t)(m)), "h"((uint16_t)(mask)) : "memory")
#define TCGEN05_WAIT_LD()      asm volatile("tcgen05.wait::ld.sync.aligned;" ::: "memory")
#define TCGEN05_FENCE_AFTER()  asm volatile("tcgen05.fence::after_thread_sync;" ::: "memory")
#define TCGEN05_FENCE_BEFORE() asm volatile("tcgen05.fence::before_thread_sync;" ::: "memory")
#define FENCE_PROXY_ASYNC()    asm volatile("fence.proxy.async.shared::cta;" ::: "memory")
#define CLUSTER_SYNC() do { \
    asm volatile("barrier.cluster.arrive.aligned;" ::: "memory"); \
    asm volatile("barrier.cluster.wait.aligned;" ::: "memory"); } while(0)

#define TCGEN05_LD_X32(r, ta) \
    asm volatile("tcgen05.ld.sync.aligned.32x32b.x32.b32 " \
        "{%0, %1, %2, %3, %4, %5, %6, %7, %8, %9, %10, %11, %12, %13, %14, %15, " \
        " %16, %17, %18, %19, %20, %21, %22, %23, %24, %25, %26, %27, %28, %29, %30, %31}, [%32];" \
        : "=r"((r)[0]), "=r"((r)[1]), "=r"((r)[2]), "=r"((r)[3]), "=r"((r)[4]), "=r"((r)[5]), "=r"((r)[6]), "=r"((r)[7]), \
          "=r"((r)[8]), "=r"((r)[9]), "=r"((r)[10]), "=r"((r)[11]), "=r"((r)[12]), "=r"((r)[13]), "=r"((r)[14]), "=r"((r)[15]), \
          "=r"((r)[16]), "=r"((r)[17]), "=r"((r)[18]), "=r"((r)[19]), "=r"((r)[20]), "=r"((r)[21]), "=r"((r)[22]), "=r"((r)[23]), \
          "=r"((r)[24]), "=r"((r)[25]), "=r"((r)[26]), "=r"((r)[27]), "=r"((r)[28]), "=r"((r)[29]), "=r"((r)[30]), "=r"((r)[31]) \
        : "r"(ta))

#define STS128F(addr, v) \
    asm volatile("st.shared.v4.f32 [%0], {%1, %2, %3, %4};" \
        :: "r"((uint32_t)(addr)), "f"((v).x), "f"((v).y), "f"((v).z), "f"((v).w) : "memory")

static constexpr uint64_t DESC_SW128 =
    (uint64_t(2) << 61) | (uint64_t(1) << 46) | (uint64_t(64) << 32) | (uint64_t(1) << 16);
#define MAKE_SMEM_DESC(a) (DESC_SW128 | ((uint64_t)((a) >> 4) & 0x3FFF))

// cta_group::2 TMA: both CTAs issue; complete_tx goes to the LEADER's barrier.
__device__ __forceinline__ void tma_load_2d_cg2(uint32_t sa, const void* map, int x, int y, uint32_t mbar) {
    asm volatile(
        "{\n\t.reg .b32 lb;\n\tand.b32 lb, %4, 0xFEFFFFFF;\n\t"
        "cp.async.bulk.tensor.2d.cta_group::2.shared::cluster.global.tile.mbarrier::complete_tx::bytes "
        "[%0], [%1, {%2, %3}], [lb];\n\t}"
        :: "r"(sa), "l"(map), "r"(x), "r"(y), "r"(mbar) : "memory");
}
__device__ __forceinline__ void mma_tf32_ss_cg2(uint32_t d, uint64_t ad, uint64_t bd, uint32_t idesc, bool acc) {
    uint32_t en = acc ? 1u : 0u, z = 0;
    asm volatile("{\n\t.reg .pred p;\n\tsetp.ne.u32 p, %5, 0;\n\t"
                 "tcgen05.mma.cta_group::2.kind::tf32 [%0], %1, %2, %3, {%4, %4, %4, %4, %4, %4, %4, %4}, p;\n\t}"
                 :: "r"(d), "l"(ad), "l"(bd), "r"(idesc), "r"(z), "r"(en) : "memory");
}
#endif // HAS_TCGEN05

// ============ K0: W2 -> tf32-rounded copy ============
__global__ void round_w2_kernel(const float* __restrict__ W2) {
    int i = blockIdx.x * 256 + threadIdx.x;
    g_W2r[i] = to_tf32(W2[i]);
}

// ============ K1: P = enc@We^T + b1, Q = dec@Wd^T ============
__global__ void proj_kernel(const float* __restrict__ enc, const float* __restrict__ dec,
                            const float* __restrict__ W1, const float* __restrict__ b1) {
    __shared__ float As[16][68];
    __shared__ float Bs[16][68];
    const int bn = blockIdx.x, bm = blockIdx.y;
    const int tid = threadIdx.x, tx = tid & 15, ty = tid >> 4;
    const bool is_enc = (bm < 16);
    const float* Asrc = is_enc ? (enc + (size_t)bm * 64 * ENC_DIM)
                               : (dec + (size_t)(bm - 16) * 64 * ENC_DIM);
    const int koff = is_enc ? 0 : ENC_DIM;
    float acc[4][4];
#pragma unroll
    for (int i = 0; i < 4; i++)
#pragma unroll
        for (int j = 0; j < 4; j++) acc[i][j] = 0.f;

    for (int kt = 0; kt < 40; kt++) {
#pragma unroll
        for (int p = 0; p < 4; p++) {
            int idx = tid + p * 256, m = idx >> 4, k = idx & 15;
            As[k][m] = Asrc[(size_t)m * ENC_DIM + kt * 16 + k];
            Bs[k][m] = W1[(size_t)(bn * 64 + m) * 1280 + koff + kt * 16 + k];
        }
        __syncthreads();
#pragma unroll
        for (int kk = 0; kk < 16; kk++) {
            float4 a = *(const float4*)&As[kk][ty * 4];
            float4 b = *(const float4*)&Bs[kk][tx * 4];
            float av[4] = {a.x, a.y, a.z, a.w}, bv[4] = {b.x, b.y, b.z, b.w};
#pragma unroll
            for (int i = 0; i < 4; i++)
#pragma unroll
                for (int j = 0; j < 4; j++) acc[i][j] += av[i] * bv[j];
        }
        __syncthreads();
    }
    float bias[4] = {0.f, 0.f, 0.f, 0.f};
    if (is_enc) {
#pragma unroll
        for (int j = 0; j < 4; j++) bias[j] = b1[bn * 64 + tx * 4 + j];
    }
#pragma unroll
    for (int i = 0; i < 4; i++) {
        int mg = bm * 64 + ty * 4 + i;
        float* dst = (mg < BT) ? &g_P[(size_t)mg * INNER] : &g_Q[(size_t)(mg - BT) * INNER];
        *(float4*)&dst[bn * 64 + tx * 4] = make_float4(acc[i][0] + bias[0], acc[i][1] + bias[1],
                                                       acc[i][2] + bias[2], acc[i][3] + bias[3]);
    }
}

// ============ K2: persistent fused cg2 GEMM; A computed in-kernel ============
static constexpr int KC = 32, NK = INNER / KC;           // 16 chunks per tile
static constexpr int STG = 4;
static constexpr int TILES_N = VOCAB / 256;              // 8
static constexpr int TOTAL_TILES = (MROWS / 256) * TILES_N;  // 2048
static constexpr int NCLUSTERS = 74;
static constexpr int TPC = (TOTAL_TILES + NCLUSTERS - 1) / NCLUSTERS;  // 28
static constexpr uint32_t IDESC_TF32_CG2 =
    (1u << 4) | (2u << 7) | (2u << 10) | (32u << 17) | (16u << 24);

static constexpr int SM_TMEMP = 0;
static constexpr int SM_FULL  = 32;                     // full[s] = 32 + 16*s
static constexpr int SM_DONE  = 128;                    // done[s] = 128 + 16*s
static constexpr int SM_FINB  = 224;                    // fin[b]  = 224 + 16*b
static constexpr int SM_FREE  = 272;                    // free[b] = 272 + 16*b
static constexpr int SM_A     = 4096;
static constexpr int AB_BYTES = 128 * KC * 4;           // 16 KB per stage per CTA
static constexpr int SM_B     = SM_A + STG * AB_BYTES;  // 69632
static constexpr int SMEM_SZ  = SM_B + STG * AB_BYTES;  // 135168
static constexpr int TX_BYTES = 2 * AB_BYTES;           // 32 KB (B only, both CTAs)
static constexpr int FULL_ARRIVES = 1 + 8;              // expect_tx + 4 A-warps x 2 CTAs

__global__ void __launch_bounds__(320, 1) __cluster_dims__(2, 1, 1) joint_gemm(
    const __grid_constant__ CUtensorMap tma_w,
    const float* __restrict__ b2, float* __restrict__ out) {
    extern __shared__ __align__(1024) char smem[];
    const int tid = threadIdx.x;
    const int cid = blockIdx.x >> 1;
    const int first = cid * TPC;
    const int nt = min(TPC, TOTAL_TILES - first);
#if HAS_TCGEN05
    const uint32_t sb = smem_to_u32(smem);
    const int wid = tid >> 5, lid = tid & 31;
    const uint32_t rank = cluster_ctarank();

    if (tid == 0) {
#pragma unroll
        for (int s = 0; s < STG; s++) {
            MBARRIER_INIT(sb + SM_FULL + 16 * s, FULL_ARRIVES);
            MBARRIER_INIT(sb + SM_DONE + 16 * s, 1);
        }
#pragma unroll
        for (int b = 0; b < 2; b++) {
            MBARRIER_INIT(sb + SM_FINB + 16 * b, 1);
            MBARRIER_INIT(sb + SM_FREE + 16 * b, 2);
        }
    }
    if (wid == 0) { TCGEN05_ALLOC_CG2(sb + SM_TMEMP, 512); TCGEN05_RELINQ_CG2(); }
    __syncthreads();
    uint32_t tmem;
    asm volatile("ld.shared.b32 %0, [%1];" : "=r"(tmem) : "r"(sb + SM_TMEMP));
    CLUSTER_SYNC();   // peer barriers live before cg2 TMA / multicast / cross-arrive

    if (wid == 5) {
        // ========= B producer: cg2 TMA (both CTAs, one elected thread) =======
        if (elect_one_pred()) {
            int dph[STG] = {0, 0, 0, 0};
            const int gend = nt * NK;
            for (int g = 0; g < gend; g++) {
                const int s = g & (STG - 1);
                if (g >= STG) { MBARRIER_WAIT_PARITY_RELAXED(sb + SM_DONE + 16 * s, dph[s]); dph[s] ^= 1; }
                const int t = first + (g >> 4);
                const int kc = g & 15;
                const int nn = t & 7;
                const uint32_t full = sb + SM_FULL + 16 * s;
                if (rank == 0) MBARRIER_EXPECT_TX(full, TX_BYTES);
                tma_load_2d_cg2(sb + SM_B + s * AB_BYTES, &tma_w, kc * KC, nn * 256 + (int)rank * 128, full);
            }
        }
    } else if (wid >= 6) {
        // ========= A producers: warps 6-9, both CTAs. Compute tanh chunk =====
        const int ct = tid - 192;          // 0..127
        const int c4 = ct & 7;             // column quad within 32-float chunk
        const int qsub = ct >> 3;          // 0..15
        int dph[STG] = {0, 0, 0, 0};
        const int gend = nt * NK;
        for (int g = 0; g < gend; g++) {
            const int s = g & (STG - 1);
            if (g >= STG) { MBARRIER_WAIT_PARITY(sb + SM_DONE + 16 * s, dph[s]); dph[s] ^= 1; }
            const int t = first + (g >> 4);
            const int kc = g & 15;
            const int mt = t >> 3;
            const int base = mt * 256 + (int)rank * 128;   // multiple of 128
            const int bt0 = base >> 6;
            const int bq = (bt0 >> 8) * 64;                // Q row block for this batch
            const float4 p0 = *(const float4*)(g_P + (size_t)bt0 * INNER + kc * KC + c4 * 4);
            const float4 p1 = *(const float4*)(g_P + (size_t)(bt0 + 1) * INNER + kc * KC + c4 * 4);
            const uint32_t abase = sb + SM_A + s * AB_BYTES;
#pragma unroll
            for (int i = 0; i < 4; i++) {
                const int u = i * 16 + qsub;
                const float4 q = *(const float4*)(g_Q + (size_t)(bq + u) * INNER + kc * KC + c4 * 4);
                const uint32_t sw = (uint32_t)((c4 ^ (u & 7)) << 4);
                float4 v0, v1;
                v0.x = to_tf32(tanh_fast(q.x + p0.x));
                v0.y = to_tf32(tanh_fast(q.y + p0.y));
                v0.z = to_tf32(tanh_fast(q.z + p0.z));
                v0.w = to_tf32(tanh_fast(q.w + p0.w));
                v1.x = to_tf32(tanh_fast(q.x + p1.x));
                v1.y = to_tf32(tanh_fast(q.y + p1.y));
                v1.z = to_tf32(tanh_fast(q.z + p1.z));
                v1.w = to_tf32(tanh_fast(q.w + p1.w));
                STS128F(abase + (uint32_t)u * 128 + sw, v0);
                STS128F(abase + (uint32_t)(u + 64) * 128 + sw, v1);
            }
            FENCE_PROXY_ASYNC();
            __syncwarp();
            if (elect_one_pred()) MBARRIER_ARRIVE_LEADER(sb + SM_FULL + 16 * s);
        }
    } else if (wid == 4) {
        // ========= MMA issuer (leader CTA only, one elected thread) ==========
        if (rank == 0 && elect_one_pred()) {
            int fph[STG] = {0, 0, 0, 0};
            int frph[2] = {0, 0};
            for (int ti = 0; ti < nt; ti++) {
                const int b = ti & 1;
                if (ti >= 2) { MBARRIER_WAIT_PARITY(sb + SM_FREE + 16 * b, frph[b]); frph[b] ^= 1; }
                const uint32_t dbuf = tmem + b * 256;
                for (int kc = 0; kc < NK; kc++) {
                    const int s = kc & (STG - 1);
                    MBARRIER_WAIT_PARITY(sb + SM_FULL + 16 * s, fph[s]); fph[s] ^= 1;
                    const uint64_t ad = MAKE_SMEM_DESC(sb + SM_A + s * AB_BYTES);
                    const uint64_t bd = MAKE_SMEM_DESC(sb + SM_B + s * AB_BYTES);
#pragma unroll
                    for (int j = 0; j < 4; j++)
                        mma_tf32_ss_cg2(dbuf, ad + 2 * j, bd + 2 * j, IDESC_TF32_CG2, (kc | j) != 0);
                    TCGEN05_COMMIT_MC_CG2(sb + SM_DONE + 16 * s, 3);
                }
                TCGEN05_COMMIT_MC_CG2(sb + SM_FINB + 16 * b, 3);
            }
        }
    } else {
        // ========= epilogue (warps 0-3, both CTAs) ===========================
        const float4* b2v = (const float4*)b2;
        int finph[2] = {0, 0};
        for (int ti = 0; ti < nt; ti++) {
            const int b = ti & 1;
            MBARRIER_WAIT_PARITY(sb + SM_FINB + 16 * b, finph[b]); finph[b] ^= 1;
            TCGEN05_FENCE_AFTER();
            const int t = first + ti;
            const int mt = t >> 3, nn = t & 7;
            const int row = mt * 256 + (int)rank * 128 + wid * 32 + lid;
            float4* orow = (float4*)(out + (size_t)row * VOCAB + nn * 256);
            const uint32_t dbuf = tmem + b * 256;
#pragma unroll 1
            for (int ch = 0; ch < 8; ch++) {
                uint32_t r[32];
                TCGEN05_LD_X32(r, dbuf + ch * 32);
                TCGEN05_WAIT_LD();
#pragma unroll
                for (int j = 0; j < 8; j++) {
                    float4 bb = b2v[nn * 64 + ch * 8 + j];
                    float4 v;
                    v.x = __uint_as_float(r[j * 4 + 0]) + bb.x;
                    v.y = __uint_as_float(r[j * 4 + 1]) + bb.y;
                    v.z = __uint_as_float(r[j * 4 + 2]) + bb.z;
                    v.w = __uint_as_float(r[j * 4 + 3]) + bb.w;
                    orow[ch * 8 + j] = v;
                }
            }
            TCGEN05_FENCE_BEFORE();
            asm volatile("bar.sync 1, 128;" ::: "memory");
            if (tid == 0) MBARRIER_ARRIVE_LEADER(sb + SM_FREE + 16 * b);
        }
    }

    __syncthreads();
    if (wid == 0) TCGEN05_DEALLOC_CG2(tmem, 512);
    CLUSTER_SYNC();
#else
    // SIMT fallback (non-'a' target only): correct, never selected on GB300.
    (void)tma_w;
    const int rank = blockIdx.x & 1;
    for (int ti = 0; ti < nt; ti++) {
        const int t = first + ti;
        const int mt = t >> 3, nn = t & 7;
        for (int e = tid; e < 128 * 256; e += 320) {
            const int r = e >> 8, c = e & 255;
            const int row = mt * 256 + rank * 128 + r;
            const int bt = row >> 6, u = row & 63, bq = (bt >> 8) * 64;
            const float* Pr = &g_P[(size_t)bt * INNER];
            const float* Qr = &g_Q[(size_t)(bq + u) * INNER];
            const float* Br = &g_W2r[(size_t)(nn * 256 + c) * INNER];
            float acc = 0.f;
            for (int k = 0; k < INNER; k++) acc += tanhf(Pr[k] + Qr[k]) * Br[k];
            out[(size_t)row * VOCAB + nn * 256 + c] = acc + b2[nn * 256 + c];
        }
    }
#endif
}

// ============ host ============
typedef CUresult (*PFN_encodeTiled)(
    CUtensorMap*, CUtensorMapDataType, cuuint32_t, void*,
    const cuuint64_t*, const cuuint64_t*, const cuuint32_t*, const cuuint32_t*,
    CUtensorMapInterleave, CUtensorMapSwizzle, CUtensorMapL2promotion, CUtensorMapFloatOOBfill);

extern "C" void kernel_launch(void* const* d_in, const int* in_sizes, int n_in,
                              void* d_out, int out_size) {
    const float* enc = (const float*)d_in[0];
    const float* dec = (const float*)d_in[1];
    const float* W1  = (const float*)d_in[2];
    const float* b1  = (const float*)d_in[3];
    const float* W2  = (const float*)d_in[4];
    const float* b2  = (const float*)d_in[5];
    float* out = (float*)d_out;

    void* wptr = nullptr; cudaGetSymbolAddress(&wptr, g_W2r);

    PFN_encodeTiled enc_fn = nullptr;
    cudaDriverEntryPointQueryResult st;
    cudaGetDriverEntryPointByVersion("cuTensorMapEncodeTiled", (void**)&enc_fn, 12050,
                                     cudaEnableDefault, &st);
    CUtensorMap mapW;
    {
        cuuint64_t dims[2] = {INNER, VOCAB};
        cuuint64_t strides[1] = {INNER * 4};
        cuuint32_t box[2] = {KC, 128};
        cuuint32_t es[2] = {1, 1};
        enc_fn(&mapW, CU_TENSOR_MAP_DATA_TYPE_FLOAT32, 2, wptr, dims, strides, box, es,
               CU_TENSOR_MAP_INTERLEAVE_NONE, CU_TENSOR_MAP_SWIZZLE_128B,
               CU_TENSOR_MAP_L2_PROMOTION_L2_128B, CU_TENSOR_MAP_FLOAT_OOB_FILL_NONE);
    }

    cudaFuncSetAttribute(joint_gemm, cudaFuncAttributeMaxDynamicSharedMemorySize, SMEM_SZ);

    round_w2_kernel<<<VOCAB * INNER / 256, 256>>>(W2);
    proj_kernel<<<dim3(8, 20), 256>>>(enc, dec, W1, b1);
    joint_gemm<<<NCLUSTERS * 2, 320, SMEM_SZ>>>(mapW, b2, out);
}

// round 9
// speedup vs baseline: 1.4506x; 1.4506x over previous
#include <cuda_runtime.h>
#include <cuda.h>
#include <cuda_bf16.h>
#include <cstdint>

static constexpr int ENC_DIM = 640;
static constexpr int INNER   = 512;
static constexpr int VOCAB   = 2048;
static constexpr int BT      = 1024;
static constexpr int MROWS   = 65536;

__device__ float g_P[BT * INNER];     // enc_proj + b1
__device__ float g_Q[256 * INNER];    // dec_proj
__device__ float g_H[(size_t)MROWS * INNER];
__device__ float g_W2r[VOCAB * INNER];

#if !defined(__CUDA_ARCH__) || defined(__CUDA_ARCH_FEAT_SM103_ALL) || defined(__CUDA_ARCH_FEAT_SM100_ALL) || defined(__CUDA_ARCH_FEAT_SM101_ALL)
#define HAS_TCGEN05 1
#else
#define HAS_TCGEN05 0
#endif

__device__ __forceinline__ uint32_t smem_to_u32(const void* ptr) {
    uint32_t a;
    asm("{ .reg .u64 t; cvta.to.shared.u64 t, %1; cvt.u32.u64 %0, t; }" : "=r"(a) : "l"(ptr));
    return a;
}
__device__ __forceinline__ float to_tf32(float x) {
    uint32_t u = __float_as_uint(x);
    u = (u + 0x1000u) & 0xFFFFE000u;
    return __uint_as_float(u);
}
__device__ __forceinline__ float tanh_fast(float x) {
    float y;
    asm("tanh.approx.f32 %0, %1;" : "=f"(y) : "f"(x));
    return y;
}

#if HAS_TCGEN05
__device__ __forceinline__ uint32_t elect_one_pred() {
    uint32_t p;
    asm volatile("{\n\t.reg .pred p;\n\telect.sync _|p, 0xFFFFFFFF;\n\tselp.b32 %0, 1, 0, p;\n\t}" : "=r"(p));
    return p;
}
__device__ __forceinline__ uint32_t cluster_ctarank() {
    uint32_t r;
    asm("mov.u32 %0, %%cluster_ctarank;" : "=r"(r));
    return r;
}
#define MBARRIER_INIT(m, c) \
    asm volatile("mbarrier.init.shared.b64 [%0], %1;" :: "r"((uint32_t)(m)), "r"((uint32_t)(c)) : "memory")
#define MBARRIER_EXPECT_TX(m, b) \
    asm volatile("mbarrier.arrive.expect_tx.shared.b64 _, [%0], %1;" :: "r"((uint32_t)(m)), "r"((uint32_t)(b)) : "memory")
// arrive on the PAIR-LEADER CTA's barrier at same offset (clear bit 24)
#define MBARRIER_ARRIVE_LEADER(m) \
    asm volatile("{\n\t.reg .b32 a;\n\tand.b32 a, %0, 0xFEFFFFFF;\n\tmbarrier.arrive.shared::cluster.b64 _, [a];\n\t}" \
        :: "r"((uint32_t)(m)) : "memory")

#define MBAR_WAIT(m, ph, SEM) do { \
    uint32_t _m = (uint32_t)(m); uint32_t _p = (uint32_t)(ph); uint32_t _d; \
    asm volatile("{\n\t.reg .pred p;\n\tmbarrier.try_wait.parity." SEM ".cta.shared::cta.b64 p, [%1], %2;\n\tselp.b32 %0, 1, 0, p;\n\t}" \
        : "=r"(_d) : "r"(_m), "r"(_p) : "memory"); \
    if (!_d) { \
        asm volatile("{\n\t.reg .pred P1;\n\tWL_%=:\n\tmbarrier.try_wait.parity." SEM ".cta.shared::cta.b64 P1, [%0], %1, 0x989680;\n\t@P1 bra.uni WD_%=;\n\tbra.uni WL_%=;\n\tWD_%=:\n\t}" \
            :: "r"(_m), "r"(_p) : "memory"); \
    } } while(0)
#define MBARRIER_WAIT_PARITY(m, p)          MBAR_WAIT(m, p, "acquire")
#define MBARRIER_WAIT_PARITY_RELAXED(m, p)  MBAR_WAIT(m, p, "relaxed")

#define TCGEN05_ALLOC_CG2(sa, n) \
    asm volatile("tcgen05.alloc.cta_group::2.sync.aligned.shared::cta.b32 [%0], %1;" :: "r"((uint32_t)(sa)), "r"((uint32_t)(n)) : "memory")
#define TCGEN05_DEALLOC_CG2(t, n) \
    asm volatile("tcgen05.dealloc.cta_group::2.sync.aligned.b32 %0, %1;" :: "r"(t), "r"((uint32_t)(n)))
#define TCGEN05_RELINQ_CG2() \
    asm volatile("tcgen05.relinquish_alloc_permit.cta_group::2.sync.aligned;")
#define TCGEN05_COMMIT_MC_CG2(m, mask) \
    asm volatile("tcgen05.commit.cta_group::2.mbarrier::arrive::one.shared::cluster.multicast::cluster.b64 [%0], %1;" \
        :: "r"((uint32_t)(m)), "h"((uint16_t)(mask)) : "memory")
#define TCGEN05_WAIT_LD()      asm volatile("tcgen05.wait::ld.sync.aligned;" ::: "memory")
#define TCGEN05_FENCE_AFTER()  asm volatile("tcgen05.fence::after_thread_sync;" ::: "memory")
#define TCGEN05_FENCE_BEFORE() asm volatile("tcgen05.fence::before_thread_sync;" ::: "memory")
#define CLUSTER_SYNC() do { \
    asm volatile("barrier.cluster.arrive.aligned;" ::: "memory"); \
    asm volatile("barrier.cluster.wait.aligned;" ::: "memory"); } while(0)

#define TCGEN05_LD_X32(r, ta) \
    asm volatile("tcgen05.ld.sync.aligned.32x32b.x32.b32 " \
        "{%0, %1, %2, %3, %4, %5, %6, %7, %8, %9, %10, %11, %12, %13, %14, %15, " \
        " %16, %17, %18, %19, %20, %21, %22, %23, %24, %25, %26, %27, %28, %29, %30, %31}, [%32];" \
        : "=r"((r)[0]), "=r"((r)[1]), "=r"((r)[2]), "=r"((r)[3]), "=r"((r)[4]), "=r"((r)[5]), "=r"((r)[6]), "=r"((r)[7]), \
          "=r"((r)[8]), "=r"((r)[9]), "=r"((r)[10]), "=r"((r)[11]), "=r"((r)[12]), "=r"((r)[13]), "=r"((r)[14]), "=r"((r)[15]), \
          "=r"((r)[16]), "=r"((r)[17]), "=r"((r)[18]), "=r"((r)[19]), "=r"((r)[20]), "=r"((r)[21]), "=r"((r)[22]), "=r"((r)[23]), \
          "=r"((r)[24]), "=r"((r)[25]), "=r"((r)[26]), "=r"((r)[27]), "=r"((r)[28]), "=r"((r)[29]), "=r"((r)[30]), "=r"((r)[31]) \
        : "r"(ta))

static constexpr uint64_t DESC_SW128 =
    (uint64_t(2) << 61) | (uint64_t(1) << 46) | (uint64_t(64) << 32) | (uint64_t(1) << 16);
#define MAKE_SMEM_DESC(a) (DESC_SW128 | ((uint64_t)((a) >> 4) & 0x3FFF))

// cta_group::2 TMA: both pair CTAs issue; complete_tx to PAIR-LEADER's barrier.
__device__ __forceinline__ void tma_load_2d_cg2(uint32_t sa, const void* map, int x, int y, uint32_t mbar) {
    asm volatile(
        "{\n\t.reg .b32 lb;\n\tand.b32 lb, %4, 0xFEFFFFFF;\n\t"
        "cp.async.bulk.tensor.2d.cta_group::2.shared::cluster.global.tile.mbarrier::complete_tx::bytes "
        "[%0], [%1, {%2, %3}], [lb];\n\t}"
        :: "r"(sa), "l"(map), "r"(x), "r"(y), "r"(mbar) : "memory");
}
// multicast TMA: data + complete_tx delivered at SAME smem offsets in every masked CTA.
__device__ __forceinline__ void tma_load_2d_mcast(uint32_t sa, const void* map, int x, int y,
                                                  uint32_t mbar, uint16_t mask) {
    asm volatile(
        "cp.async.bulk.tensor.2d.shared::cluster.global.tile.mbarrier::complete_tx::bytes.multicast::cluster "
        "[%0], [%1, {%2, %3}], [%4], %5;"
        :: "r"(sa), "l"(map), "r"(x), "r"(y), "r"(mbar), "h"(mask) : "memory");
}
__device__ __forceinline__ void mma_tf32_ss_cg2(uint32_t d, uint64_t ad, uint64_t bd, uint32_t idesc, bool acc) {
    uint32_t en = acc ? 1u : 0u, z = 0;
    asm volatile("{\n\t.reg .pred p;\n\tsetp.ne.u32 p, %5, 0;\n\t"
                 "tcgen05.mma.cta_group::2.kind::tf32 [%0], %1, %2, %3, {%4, %4, %4, %4, %4, %4, %4, %4}, p;\n\t}"
                 :: "r"(d), "l"(ad), "l"(bd), "r"(idesc), "r"(z), "r"(en) : "memory");
}
#endif // HAS_TCGEN05

// ============ K0: W2 -> tf32-rounded copy ============
__global__ void round_w2_kernel(const float* __restrict__ W2) {
    int i = blockIdx.x * 256 + threadIdx.x;
    g_W2r[i] = to_tf32(W2[i]);
}

// ============ K1: P = enc@We^T + b1, Q = dec@Wd^T ============
__global__ void proj_kernel(const float* __restrict__ enc, const float* __restrict__ dec,
                            const float* __restrict__ W1, const float* __restrict__ b1) {
    __shared__ float As[16][68];
    __shared__ float Bs[16][68];
    const int bn = blockIdx.x, bm = blockIdx.y;
    const int tid = threadIdx.x, tx = tid & 15, ty = tid >> 4;
    const bool is_enc = (bm < 16);
    const float* Asrc = is_enc ? (enc + (size_t)bm * 64 * ENC_DIM)
                               : (dec + (size_t)(bm - 16) * 64 * ENC_DIM);
    const int koff = is_enc ? 0 : ENC_DIM;
    float acc[4][4];
#pragma unroll
    for (int i = 0; i < 4; i++)
#pragma unroll
        for (int j = 0; j < 4; j++) acc[i][j] = 0.f;

    for (int kt = 0; kt < 40; kt++) {
#pragma unroll
        for (int p = 0; p < 4; p++) {
            int idx = tid + p * 256, m = idx >> 4, k = idx & 15;
            As[k][m] = Asrc[(size_t)m * ENC_DIM + kt * 16 + k];
            Bs[k][m] = W1[(size_t)(bn * 64 + m) * 1280 + koff + kt * 16 + k];
        }
        __syncthreads();
#pragma unroll
        for (int kk = 0; kk < 16; kk++) {
            float4 a = *(const float4*)&As[kk][ty * 4];
            float4 b = *(const float4*)&Bs[kk][tx * 4];
            float av[4] = {a.x, a.y, a.z, a.w}, bv[4] = {b.x, b.y, b.z, b.w};
#pragma unroll
            for (int i = 0; i < 4; i++)
#pragma unroll
                for (int j = 0; j < 4; j++) acc[i][j] += av[i] * bv[j];
        }
        __syncthreads();
    }
    float bias[4] = {0.f, 0.f, 0.f, 0.f};
    if (is_enc) {
#pragma unroll
        for (int j = 0; j < 4; j++) bias[j] = b1[bn * 64 + tx * 4 + j];
    }
#pragma unroll
    for (int i = 0; i < 4; i++) {
        int mg = bm * 64 + ty * 4 + i;
        float* dst = (mg < BT) ? &g_P[(size_t)mg * INNER] : &g_Q[(size_t)(mg - BT) * INNER];
        *(float4*)&dst[bn * 64 + tx * 4] = make_float4(acc[i][0] + bias[0], acc[i][1] + bias[1],
                                                       acc[i][2] + bias[2], acc[i][3] + bias[3]);
    }
}

// ============ K2: H = tf32(tanh(P + Q)), vectorized ============
__global__ void h_kernel() {
    __shared__ float4 sPB[128];
    const int bt = blockIdx.x, b = bt >> 8;
    if (threadIdx.x < 128)
        sPB[threadIdx.x] = ((const float4*)(g_P + (size_t)bt * INNER))[threadIdx.x];
    __syncthreads();
    const float4* Qb = (const float4*)(g_Q + (size_t)b * 64 * INNER);
    float4* Hrow = (float4*)(g_H + (size_t)bt * 64 * INNER);
#pragma unroll 4
    for (int i = threadIdx.x; i < 64 * 128; i += 256) {
        const float4 p = sPB[i & 127];
        const float4 q = Qb[i];
        float4 v;
        v.x = to_tf32(tanh_fast(p.x + q.x));
        v.y = to_tf32(tanh_fast(p.y + q.y));
        v.z = to_tf32(tanh_fast(p.z + q.z));
        v.w = to_tf32(tanh_fast(p.w + q.w));
        Hrow[i] = v;
    }
}

// ============ K3: persistent cluster-4 cg2 GEMM, B multicast ============
static constexpr int KC = 32, NK = INNER / KC;           // 16 chunks per tile
static constexpr int STG = 4;
static constexpr int QSTEPS = (MROWS / 512) * (VOCAB / 256);  // 1024 pair-steps
static constexpr int NCLUST = 32;
static constexpr int TPC = QSTEPS / NCLUST;              // 32, exact
static constexpr int THREADS = 192;                      // EXACTLY 6 warps
static constexpr uint32_t IDESC_TF32_CG2 =
    (1u << 4) | (2u << 7) | (2u << 10) | (32u << 17) | (16u << 24);

static constexpr int SM_TMEMP = 0;
static constexpr int SM_FULL  = 32;                     // full[s] = 32 + 16*s
static constexpr int SM_DONE  = 128;                    // done[s] = 128 + 16*s
static constexpr int SM_FINB  = 224;                    // fin[b]  = 224 + 16*b
static constexpr int SM_FREE  = 272;                    // free[b] = 272 + 16*b
static constexpr int SM_A     = 4096;
static constexpr int AB_BYTES = 128 * KC * 4;           // 16 KB per stage per CTA
static constexpr int SM_B     = SM_A + STG * AB_BYTES;  // 69632
static constexpr int SMEM_SZ  = SM_B + STG * AB_BYTES;  // 135168
static constexpr int TX_LDR   = 3 * AB_BYTES;           // A both halves + own B half
static constexpr int TX_NLD   = AB_BYTES;               // own B half only

__global__ void __launch_bounds__(THREADS, 1) __cluster_dims__(4, 1, 1) joint_gemm(
    const __grid_constant__ CUtensorMap tma_h,
    const __grid_constant__ CUtensorMap tma_w,
    const float* __restrict__ b2, float* __restrict__ out) {
    extern __shared__ __align__(1024) char smem[];
    const int tid = threadIdx.x;
    const int cid = blockIdx.x >> 2;
    const int first = cid * TPC;
    const int nt = TPC;
#if HAS_TCGEN05
    const uint32_t sb = smem_to_u32(smem);
    const int wid = tid >> 5, lid = tid & 31;
    const uint32_t rank = cluster_ctarank();
    const int pair = (int)rank >> 1;        // 0 or 1
    const int half = (int)rank & 1;         // M/N half within pair
    const bool leader = (half == 0);

    if (tid == 0) {
#pragma unroll
        for (int s = 0; s < STG; s++) {
            MBARRIER_INIT(sb + SM_FULL + 16 * s, leader ? 2 : 1);  // expect-arrive (+peer fwd)
            MBARRIER_INIT(sb + SM_DONE + 16 * s, 2);               // commits from BOTH pairs
        }
#pragma unroll
        for (int b = 0; b < 2; b++) {
            MBARRIER_INIT(sb + SM_FINB + 16 * b, 1);
            MBARRIER_INIT(sb + SM_FREE + 16 * b, 2);               // both pair CTAs' epilogues
        }
    }
    if (wid == 0) { TCGEN05_ALLOC_CG2(sb + SM_TMEMP, 512); TCGEN05_RELINQ_CG2(); }
    __syncthreads();
    uint32_t tmem;
    asm volatile("ld.shared.b32 %0, [%1];" : "=r"(tmem) : "r"(sb + SM_TMEMP));
    CLUSTER_SYNC();   // all barriers live before cg2 TMA / multicast / cross-arrives

    if (wid == 5) {
        // ===== producer: expect_tx + A (cg2) + B (multicast, ranks 0,1 only) =====
        if (elect_one_pred()) {
            int dph[STG] = {0, 0, 0, 0};
            const int gend = nt * NK;
            for (int g = 0; g < gend; g++) {
                const int s = g & (STG - 1);
                if (g >= STG) { MBARRIER_WAIT_PARITY_RELAXED(sb + SM_DONE + 16 * s, dph[s]); dph[s] ^= 1; }
                const int q = first + (g >> 4);
                const int kc = g & 15;
                const int nn = q & 7, mtq = q >> 3;
                const int mt = mtq * 2 + pair;
                const uint32_t full = sb + SM_FULL + 16 * s;
                MBARRIER_EXPECT_TX(full, leader ? TX_LDR : TX_NLD);
                tma_load_2d_cg2(sb + SM_A + s * AB_BYTES, &tma_h, kc * KC, mt * 256 + half * 128, full);
                if (rank < 2)
                    tma_load_2d_mcast(sb + SM_B + s * AB_BYTES, &tma_w, kc * KC,
                                      nn * 256 + (int)rank * 128, full,
                                      rank == 0 ? (uint16_t)0x5 : (uint16_t)0xA);
            }
        }
    } else if (wid == 4) {
        if (leader) {
            // ===== MMA issuer (pair leaders: ranks 0, 2) =====
            if (elect_one_pred()) {
                const uint16_t pmask = (rank == 0) ? (uint16_t)0x3 : (uint16_t)0xC;
                int fph[STG] = {0, 0, 0, 0};
                int frph[2] = {0, 0};
                for (int ti = 0; ti < nt; ti++) {
                    const int b = ti & 1;
                    if (ti >= 2) { MBARRIER_WAIT_PARITY(sb + SM_FREE + 16 * b, frph[b]); frph[b] ^= 1; }
                    const uint32_t dbuf = tmem + b * 256;
                    for (int kc = 0; kc < NK; kc++) {
                        const int s = kc & (STG - 1);
                        MBARRIER_WAIT_PARITY_RELAXED(sb + SM_FULL + 16 * s, fph[s]); fph[s] ^= 1;
                        const uint64_t ad = MAKE_SMEM_DESC(sb + SM_A + s * AB_BYTES);
                        const uint64_t bd = MAKE_SMEM_DESC(sb + SM_B + s * AB_BYTES);
#pragma unroll
                        for (int j = 0; j < 4; j++)
                            mma_tf32_ss_cg2(dbuf, ad + 2 * j, bd + 2 * j, IDESC_TF32_CG2, (kc | j) != 0);
                        TCGEN05_COMMIT_MC_CG2(sb + SM_DONE + 16 * s, 0xF);   // all 4 CTAs' done
                    }
                    TCGEN05_COMMIT_MC_CG2(sb + SM_FINB + 16 * b, pmask);
                }
            }
        } else {
            // ===== forwarder (ranks 1, 3): own B ready -> arrive pair-leader's full =====
            if (elect_one_pred()) {
                int fph[STG] = {0, 0, 0, 0};
                const int gend = nt * NK;
                for (int g = 0; g < gend; g++) {
                    const int s = g & (STG - 1);
                    MBARRIER_WAIT_PARITY_RELAXED(sb + SM_FULL + 16 * s, fph[s]); fph[s] ^= 1;
                    MBARRIER_ARRIVE_LEADER(sb + SM_FULL + 16 * s);
                }
            }
        }
    } else {
        // ===== epilogue (warps 0-3 ONLY, all CTAs) =====
        const float4* b2v = (const float4*)b2;
        int finph[2] = {0, 0};
        for (int ti = 0; ti < nt; ti++) {
            const int b = ti & 1;
            MBARRIER_WAIT_PARITY(sb + SM_FINB + 16 * b, finph[b]); finph[b] ^= 1;
            TCGEN05_FENCE_AFTER();
            const int q = first + ti;
            const int nn = q & 7, mtq = q >> 3;
            const int mt = mtq * 2 + pair;
            const int row = mt * 256 + half * 128 + wid * 32 + lid;
            float4* orow = (float4*)(out + (size_t)row * VOCAB + nn * 256);
            const uint32_t dbuf = tmem + b * 256;
#pragma unroll 1
            for (int ch = 0; ch < 8; ch++) {
                uint32_t r[32];
                TCGEN05_LD_X32(r, dbuf + ch * 32);
                TCGEN05_WAIT_LD();
#pragma unroll
                for (int j = 0; j < 8; j++) {
                    float4 bb = b2v[nn * 64 + ch * 8 + j];
                    float4 v;
                    v.x = __uint_as_float(r[j * 4 + 0]) + bb.x;
                    v.y = __uint_as_float(r[j * 4 + 1]) + bb.y;
                    v.z = __uint_as_float(r[j * 4 + 2]) + bb.z;
                    v.w = __uint_as_float(r[j * 4 + 3]) + bb.w;
                    orow[ch * 8 + j] = v;
                }
            }
            TCGEN05_FENCE_BEFORE();
            asm volatile("bar.sync 1, 128;" ::: "memory");   // exactly warps 0-3
            if (tid == 0) MBARRIER_ARRIVE_LEADER(sb + SM_FREE + 16 * b);
        }
    }

    __syncthreads();
    if (wid == 0) TCGEN05_DEALLOC_CG2(tmem, 512);
    CLUSTER_SYNC();
#else
    // SIMT fallback (non-'a' target only): correct, never selected on GB300.
    (void)tma_h; (void)tma_w;
    const int rank = blockIdx.x & 3;
    for (int ti = 0; ti < nt; ti++) {
        const int q = first + ti;
        const int nn = q & 7, mtq = q >> 3;
        const int mt = mtq * 2 + (rank >> 1);
        for (int e = tid; e < 128 * 256; e += THREADS) {
            const int r = e >> 8, c = e & 255;
            const int row = mt * 256 + (rank & 1) * 128 + r;
            const float* Ar = &g_H[(size_t)row * INNER];
            const float* Br = &g_W2r[(size_t)(nn * 256 + c) * INNER];
            float acc = 0.f;
            for (int k = 0; k < INNER; k++) acc += Ar[k] * Br[k];
            out[(size_t)row * VOCAB + nn * 256 + c] = acc + b2[nn * 256 + c];
        }
    }
#endif
}

// ============ host ============
typedef CUresult (*PFN_encodeTiled)(
    CUtensorMap*, CUtensorMapDataType, cuuint32_t, void*,
    const cuuint64_t*, const cuuint64_t*, const cuuint32_t*, const cuuint32_t*,
    CUtensorMapInterleave, CUtensorMapSwizzle, CUtensorMapL2promotion, CUtensorMapFloatOOBfill);

static void make_map(PFN_encodeTiled fn, CUtensorMap* m, void* ptr,
                     uint64_t d0, uint64_t d1, uint32_t b0, uint32_t b1) {
    cuuint64_t dims[2] = {d0, d1};
    cuuint64_t strides[1] = {d0 * 4};
    cuuint32_t box[2] = {b0, b1};
    cuuint32_t es[2] = {1, 1};
    fn(m, CU_TENSOR_MAP_DATA_TYPE_FLOAT32, 2, ptr, dims, strides, box, es,
       CU_TENSOR_MAP_INTERLEAVE_NONE, CU_TENSOR_MAP_SWIZZLE_128B,
       CU_TENSOR_MAP_L2_PROMOTION_L2_128B, CU_TENSOR_MAP_FLOAT_OOB_FILL_NONE);
}

extern "C" void kernel_launch(void* const* d_in, const int* in_sizes, int n_in,
                              void* d_out, int out_size) {
    const float* enc = (const float*)d_in[0];
    const float* dec = (const float*)d_in[1];
    const float* W1  = (const float*)d_in[2];
    const float* b1  = (const float*)d_in[3];
    const float* W2  = (const float*)d_in[4];
    const float* b2  = (const float*)d_in[5];
    float* out = (float*)d_out;

    void* hptr = nullptr; cudaGetSymbolAddress(&hptr, g_H);
    void* wptr = nullptr; cudaGetSymbolAddress(&wptr, g_W2r);

    PFN_encodeTiled enc_fn = nullptr;
    cudaDriverEntryPointQueryResult st;
    cudaGetDriverEntryPointByVersion("cuTensorMapEncodeTiled", (void**)&enc_fn, 12050,
                                     cudaEnableDefault, &st);
    CUtensorMap mapH, mapW;
    make_map(enc_fn, &mapH, hptr, INNER, MROWS, KC, 128);
    make_map(enc_fn, &mapW, wptr, INNER, VOCAB, KC, 128);

    cudaFuncSetAttribute(joint_gemm, cudaFuncAttributeMaxDynamicSharedMemorySize, SMEM_SZ);

    round_w2_kernel<<<VOCAB * INNER / 256, 256>>>(W2);
    proj_kernel<<<dim3(8, 20), 256>>>(enc, dec, W1, b1);
    h_kernel<<<BT, 256>>>();
    joint_gemm<<<NCLUST * 4, THREADS, SMEM_SZ>>>(mapH, mapW, b2, out);
}

// round 10
// speedup vs baseline: 1.7060x; 1.1761x over previous
#include <cuda_runtime.h>
#include <cuda.h>
#include <cuda_bf16.h>
#include <cuda_fp16.h>
#include <cstdint>

static constexpr int ENC_DIM = 640;
static constexpr int INNER   = 512;
static constexpr int VOCAB   = 2048;
static constexpr int BT      = 1024;
static constexpr int MROWS   = 65536;

__device__ float  g_P[BT * INNER];     // enc_proj + b1
__device__ float  g_Q[256 * INNER];    // dec_proj
__device__ __half g_H[(size_t)MROWS * INNER];   // tanh(...) in fp16 (67 MB)
__device__ __half g_W2r[VOCAB * INNER];         // W2 in fp16 (2 MB)

#if !defined(__CUDA_ARCH__) || defined(__CUDA_ARCH_FEAT_SM103_ALL) || defined(__CUDA_ARCH_FEAT_SM100_ALL) || defined(__CUDA_ARCH_FEAT_SM101_ALL)
#define HAS_TCGEN05 1
#else
#define HAS_TCGEN05 0
#endif

__device__ __forceinline__ uint32_t smem_to_u32(const void* ptr) {
    uint32_t a;
    asm("{ .reg .u64 t; cvta.to.shared.u64 t, %1; cvt.u32.u64 %0, t; }" : "=r"(a) : "l"(ptr));
    return a;
}
__device__ __forceinline__ float tanh_fast(float x) {
    float y;
    asm("tanh.approx.f32 %0, %1;" : "=f"(y) : "f"(x));
    return y;
}

#if HAS_TCGEN05
__device__ __forceinline__ uint32_t elect_one_pred() {
    uint32_t p;
    asm volatile("{\n\t.reg .pred p;\n\telect.sync _|p, 0xFFFFFFFF;\n\tselp.b32 %0, 1, 0, p;\n\t}" : "=r"(p));
    return p;
}
__device__ __forceinline__ uint32_t cluster_ctarank() {
    uint32_t r;
    asm("mov.u32 %0, %%cluster_ctarank;" : "=r"(r));
    return r;
}
#define MBARRIER_INIT(m, c) \
    asm volatile("mbarrier.init.shared.b64 [%0], %1;" :: "r"((uint32_t)(m)), "r"((uint32_t)(c)) : "memory")
#define MBARRIER_EXPECT_TX(m, b) \
    asm volatile("mbarrier.arrive.expect_tx.shared.b64 _, [%0], %1;" :: "r"((uint32_t)(m)), "r"((uint32_t)(b)) : "memory")
// arrive on the PAIR-LEADER CTA's barrier at same offset (clear bit 24)
#define MBARRIER_ARRIVE_LEADER(m) \
    asm volatile("{\n\t.reg .b32 a;\n\tand.b32 a, %0, 0xFEFFFFFF;\n\tmbarrier.arrive.shared::cluster.b64 _, [a];\n\t}" \
        :: "r"((uint32_t)(m)) : "memory")

#define MBAR_WAIT(m, ph, SEM) do { \
    uint32_t _m = (uint32_t)(m); uint32_t _p = (uint32_t)(ph); uint32_t _d; \
    asm volatile("{\n\t.reg .pred p;\n\tmbarrier.try_wait.parity." SEM ".cta.shared::cta.b64 p, [%1], %2;\n\tselp.b32 %0, 1, 0, p;\n\t}" \
        : "=r"(_d) : "r"(_m), "r"(_p) : "memory"); \
    if (!_d) { \
        asm volatile("{\n\t.reg .pred P1;\n\tWL_%=:\n\tmbarrier.try_wait.parity." SEM ".cta.shared::cta.b64 P1, [%0], %1, 0x989680;\n\t@P1 bra.uni WD_%=;\n\tbra.uni WL_%=;\n\tWD_%=:\n\t}" \
            :: "r"(_m), "r"(_p) : "memory"); \
    } } while(0)
#define MBARRIER_WAIT_PARITY(m, p)          MBAR_WAIT(m, p, "acquire")
#define MBARRIER_WAIT_PARITY_RELAXED(m, p)  MBAR_WAIT(m, p, "relaxed")

#define TCGEN05_ALLOC_CG2(sa, n) \
    asm volatile("tcgen05.alloc.cta_group::2.sync.aligned.shared::cta.b32 [%0], %1;" :: "r"((uint32_t)(sa)), "r"((uint32_t)(n)) : "memory")
#define TCGEN05_DEALLOC_CG2(t, n) \
    asm volatile("tcgen05.dealloc.cta_group::2.sync.aligned.b32 %0, %1;" :: "r"(t), "r"((uint32_t)(n)))
#define TCGEN05_RELINQ_CG2() \
    asm volatile("tcgen05.relinquish_alloc_permit.cta_group::2.sync.aligned;")
#define TCGEN05_COMMIT_MC_CG2(m, mask) \
    asm volatile("tcgen05.commit.cta_group::2.mbarrier::arrive::one.shared::cluster.multicast::cluster.b64 [%0], %1;" \
        :: "r"((uint32_t)(m)), "h"((uint16_t)(mask)) : "memory")
#define TCGEN05_WAIT_LD()      asm volatile("tcgen05.wait::ld.sync.aligned;" ::: "memory")
#define TCGEN05_FENCE_AFTER()  asm volatile("tcgen05.fence::after_thread_sync;" ::: "memory")
#define TCGEN05_FENCE_BEFORE() asm volatile("tcgen05.fence::before_thread_sync;" ::: "memory")
#define CLUSTER_SYNC() do { \
    asm volatile("barrier.cluster.arrive.aligned;" ::: "memory"); \
    asm volatile("barrier.cluster.wait.aligned;" ::: "memory"); } while(0)

#define TCGEN05_LD_X32(r, ta) \
    asm volatile("tcgen05.ld.sync.aligned.32x32b.x32.b32 " \
        "{%0, %1, %2, %3, %4, %5, %6, %7, %8, %9, %10, %11, %12, %13, %14, %15, " \
        " %16, %17, %18, %19, %20, %21, %22, %23, %24, %25, %26, %27, %28, %29, %30, %31}, [%32];" \
        : "=r"((r)[0]), "=r"((r)[1]), "=r"((r)[2]), "=r"((r)[3]), "=r"((r)[4]), "=r"((r)[5]), "=r"((r)[6]), "=r"((r)[7]), \
          "=r"((r)[8]), "=r"((r)[9]), "=r"((r)[10]), "=r"((r)[11]), "=r"((r)[12]), "=r"((r)[13]), "=r"((r)[14]), "=r"((r)[15]), \
          "=r"((r)[16]), "=r"((r)[17]), "=r"((r)[18]), "=r"((r)[19]), "=r"((r)[20]), "=r"((r)[21]), "=r"((r)[22]), "=r"((r)[23]), \
          "=r"((r)[24]), "=r"((r)[25]), "=r"((r)[26]), "=r"((r)[27]), "=r"((r)[28]), "=r"((r)[29]), "=r"((r)[30]), "=r"((r)[31]) \
        : "r"(ta))

static constexpr uint64_t DESC_SW128 =
    (uint64_t(2) << 61) | (uint64_t(1) << 46) | (uint64_t(64) << 32) | (uint64_t(1) << 16);
#define MAKE_SMEM_DESC(a) (DESC_SW128 | ((uint64_t)((a) >> 4) & 0x3FFF))

// cta_group::2 TMA: both pair CTAs issue; complete_tx to PAIR-LEADER's barrier.
__device__ __forceinline__ void tma_load_2d_cg2(uint32_t sa, const void* map, int x, int y, uint32_t mbar) {
    asm volatile(
        "{\n\t.reg .b32 lb;\n\tand.b32 lb, %4, 0xFEFFFFFF;\n\t"
        "cp.async.bulk.tensor.2d.cta_group::2.shared::cluster.global.tile.mbarrier::complete_tx::bytes "
        "[%0], [%1, {%2, %3}], [lb];\n\t}"
        :: "r"(sa), "l"(map), "r"(x), "r"(y), "r"(mbar) : "memory");
}
// multicast TMA: data + complete_tx delivered at SAME smem offsets in every masked CTA.
__device__ __forceinline__ void tma_load_2d_mcast(uint32_t sa, const void* map, int x, int y,
                                                  uint32_t mbar, uint16_t mask) {
    asm volatile(
        "cp.async.bulk.tensor.2d.shared::cluster.global.tile.mbarrier::complete_tx::bytes.multicast::cluster "
        "[%0], [%1, {%2, %3}], [%4], %5;"
        :: "r"(sa), "l"(map), "r"(x), "r"(y), "r"(mbar), "h"(mask) : "memory");
}
__device__ __forceinline__ void mma_f16_ss_cg2(uint32_t d, uint64_t ad, uint64_t bd, uint32_t idesc, bool acc) {
    uint32_t en = acc ? 1u : 0u, z = 0;
    asm volatile("{\n\t.reg .pred p;\n\tsetp.ne.u32 p, %5, 0;\n\t"
                 "tcgen05.mma.cta_group::2.kind::f16 [%0], %1, %2, %3, {%4, %4, %4, %4, %4, %4, %4, %4}, p;\n\t}"
                 :: "r"(d), "l"(ad), "l"(bd), "r"(idesc), "r"(z), "r"(en) : "memory");
}
#endif // HAS_TCGEN05

// ============ K0: W2 -> fp16 copy ============
__global__ void round_w2_kernel(const float* __restrict__ W2) {
    int i = blockIdx.x * 256 + threadIdx.x;   // grid covers VOCAB*INNER/2
    float2 v = ((const float2*)W2)[i];
    ((__half2*)g_W2r)[i] = __floats2half2_rn(v.x, v.y);
}

// ============ K1: P = enc@We^T + b1, Q = dec@Wd^T ============
__global__ void proj_kernel(const float* __restrict__ enc, const float* __restrict__ dec,
                            const float* __restrict__ W1, const float* __restrict__ b1) {
    __shared__ float As[16][68];
    __shared__ float Bs[16][68];
    const int bn = blockIdx.x, bm = blockIdx.y;
    const int tid = threadIdx.x, tx = tid & 15, ty = tid >> 4;
    const bool is_enc = (bm < 16);
    const float* Asrc = is_enc ? (enc + (size_t)bm * 64 * ENC_DIM)
                               : (dec + (size_t)(bm - 16) * 64 * ENC_DIM);
    const int koff = is_enc ? 0 : ENC_DIM;
    float acc[4][4];
#pragma unroll
    for (int i = 0; i < 4; i++)
#pragma unroll
        for (int j = 0; j < 4; j++) acc[i][j] = 0.f;

    for (int kt = 0; kt < 40; kt++) {
#pragma unroll
        for (int p = 0; p < 4; p++) {
            int idx = tid + p * 256, m = idx >> 4, k = idx & 15;
            As[k][m] = Asrc[(size_t)m * ENC_DIM + kt * 16 + k];
            Bs[k][m] = W1[(size_t)(bn * 64 + m) * 1280 + koff + kt * 16 + k];
        }
        __syncthreads();
#pragma unroll
        for (int kk = 0; kk < 16; kk++) {
            float4 a = *(const float4*)&As[kk][ty * 4];
            float4 b = *(const float4*)&Bs[kk][tx * 4];
            float av[4] = {a.x, a.y, a.z, a.w}, bv[4] = {b.x, b.y, b.z, b.w};
#pragma unroll
            for (int i = 0; i < 4; i++)
#pragma unroll
                for (int j = 0; j < 4; j++) acc[i][j] += av[i] * bv[j];
        }
        __syncthreads();
    }
    float bias[4] = {0.f, 0.f, 0.f, 0.f};
    if (is_enc) {
#pragma unroll
        for (int j = 0; j < 4; j++) bias[j] = b1[bn * 64 + tx * 4 + j];
    }
#pragma unroll
    for (int i = 0; i < 4; i++) {
        int mg = bm * 64 + ty * 4 + i;
        float* dst = (mg < BT) ? &g_P[(size_t)mg * INNER] : &g_Q[(size_t)(mg - BT) * INNER];
        *(float4*)&dst[bn * 64 + tx * 4] = make_float4(acc[i][0] + bias[0], acc[i][1] + bias[1],
                                                       acc[i][2] + bias[2], acc[i][3] + bias[3]);
    }
}

// ============ K2: H = fp16(tanh(P + Q)) ============
__global__ void h_kernel() {
    __shared__ float4 sPB[128];
    const int bt = blockIdx.x, b = bt >> 8;
    if (threadIdx.x < 128)
        sPB[threadIdx.x] = ((const float4*)(g_P + (size_t)bt * INNER))[threadIdx.x];
    __syncthreads();
    const float4* Qb = (const float4*)(g_Q + (size_t)b * 64 * INNER);
    uint2* Hrow = (uint2*)(g_H + (size_t)bt * 64 * INNER);
#pragma unroll 4
    for (int i = threadIdx.x; i < 64 * 128; i += 256) {
        const float4 p = sPB[i & 127];
        const float4 q = Qb[i];
        __half2 h0 = __floats2half2_rn(tanh_fast(p.x + q.x), tanh_fast(p.y + q.y));
        __half2 h1 = __floats2half2_rn(tanh_fast(p.z + q.z), tanh_fast(p.w + q.w));
        uint2 u;
        u.x = *(uint32_t*)&h0;
        u.y = *(uint32_t*)&h1;
        Hrow[i] = u;
    }
}

// ============ K3: persistent cluster-4 cg2 fp16 GEMM, B multicast ============
static constexpr int KC = 64, NK = INNER / KC;           // 64 fp16 = 128B row; 8 chunks
static constexpr int STG = 4;
static constexpr int QSTEPS = (MROWS / 512) * (VOCAB / 256);  // 1024 pair-steps
static constexpr int NCLUST = 32;
static constexpr int TPC = QSTEPS / NCLUST;              // 32, exact
static constexpr int THREADS = 192;                      // exactly 6 warps
// kind::f16, fp16 inputs (atype=btype=0), fp32 accum, M=256 (cg2), N=256
static constexpr uint32_t IDESC_F16_CG2 =
    (1u << 4) | (32u << 17) | (16u << 24);

static constexpr int SM_TMEMP = 0;
static constexpr int SM_FULL  = 32;                     // full[s] = 32 + 16*s
static constexpr int SM_DONE  = 128;                    // done[s] = 128 + 16*s
static constexpr int SM_FINB  = 224;                    // fin[b]  = 224 + 16*b
static constexpr int SM_FREE  = 272;                    // free[b] = 272 + 16*b
static constexpr int SM_A     = 4096;
static constexpr int AB_BYTES = 128 * KC * 2;           // 16 KB per stage per CTA
static constexpr int SM_B     = SM_A + STG * AB_BYTES;  // 69632
static constexpr int SMEM_SZ  = SM_B + STG * AB_BYTES;  // 135168
static constexpr int TX_LDR   = 3 * AB_BYTES;           // A both halves + own B half
static constexpr int TX_NLD   = AB_BYTES;               // own B half only

__global__ void __launch_bounds__(THREADS, 1) __cluster_dims__(4, 1, 1) joint_gemm(
    const __grid_constant__ CUtensorMap tma_h,
    const __grid_constant__ CUtensorMap tma_w,
    const float* __restrict__ b2, float* __restrict__ out) {
    extern __shared__ __align__(1024) char smem[];
    const int tid = threadIdx.x;
    const int cid = blockIdx.x >> 2;
    const int first = cid * TPC;
    const int nt = TPC;
#if HAS_TCGEN05
    const uint32_t sb = smem_to_u32(smem);
    const int wid = tid >> 5, lid = tid & 31;
    const uint32_t rank = cluster_ctarank();
    const int pair = (int)rank >> 1;        // 0 or 1
    const int half = (int)rank & 1;         // M/N half within pair
    const bool leader = (half == 0);

    if (tid == 0) {
#pragma unroll
        for (int s = 0; s < STG; s++) {
            MBARRIER_INIT(sb + SM_FULL + 16 * s, leader ? 2 : 1);  // expect-arrive (+peer fwd)
            MBARRIER_INIT(sb + SM_DONE + 16 * s, 2);               // commits from BOTH pairs
        }
#pragma unroll
        for (int b = 0; b < 2; b++) {
            MBARRIER_INIT(sb + SM_FINB + 16 * b, 1);
            MBARRIER_INIT(sb + SM_FREE + 16 * b, 2);               // both pair CTAs' epilogues
        }
    }
    if (wid == 0) { TCGEN05_ALLOC_CG2(sb + SM_TMEMP, 512); TCGEN05_RELINQ_CG2(); }
    __syncthreads();
    uint32_t tmem;
    asm volatile("ld.shared.b32 %0, [%1];" : "=r"(tmem) : "r"(sb + SM_TMEMP));
    CLUSTER_SYNC();   // all barriers live before cg2 TMA / multicast / cross-arrives

    if (wid == 5) {
        // ===== producer: expect_tx + A (cg2) + B (multicast, ranks 0,1 only) =====
        if (elect_one_pred()) {
            int dph[STG] = {0, 0, 0, 0};
            const int gend = nt * NK;
            for (int g = 0; g < gend; g++) {
                const int s = g & (STG - 1);
                if (g >= STG) { MBARRIER_WAIT_PARITY_RELAXED(sb + SM_DONE + 16 * s, dph[s]); dph[s] ^= 1; }
                const int q = first + (g >> 3);
                const int kc = g & 7;
                const int nn = q & 7, mtq = q >> 3;
                const int mt = mtq * 2 + pair;
                const uint32_t full = sb + SM_FULL + 16 * s;
                MBARRIER_EXPECT_TX(full, leader ? TX_LDR : TX_NLD);
                tma_load_2d_cg2(sb + SM_A + s * AB_BYTES, &tma_h, kc * KC, mt * 256 + half * 128, full);
                if (rank < 2)
                    tma_load_2d_mcast(sb + SM_B + s * AB_BYTES, &tma_w, kc * KC,
                                      nn * 256 + (int)rank * 128, full,
                                      rank == 0 ? (uint16_t)0x5 : (uint16_t)0xA);
            }
        }
    } else if (wid == 4) {
        if (leader) {
            // ===== MMA issuer (pair leaders: ranks 0, 2) =====
            if (elect_one_pred()) {
                const uint16_t pmask = (rank == 0) ? (uint16_t)0x3 : (uint16_t)0xC;
                int fph[STG] = {0, 0, 0, 0};
                int frph[2] = {0, 0};
                for (int ti = 0; ti < nt; ti++) {
                    const int b = ti & 1;
                    if (ti >= 2) { MBARRIER_WAIT_PARITY(sb + SM_FREE + 16 * b, frph[b]); frph[b] ^= 1; }
                    const uint32_t dbuf = tmem + b * 256;
                    for (int kc = 0; kc < NK; kc++) {
                        const int s = kc & (STG - 1);
                        MBARRIER_WAIT_PARITY_RELAXED(sb + SM_FULL + 16 * s, fph[s]); fph[s] ^= 1;
                        const uint64_t ad = MAKE_SMEM_DESC(sb + SM_A + s * AB_BYTES);
                        const uint64_t bd = MAKE_SMEM_DESC(sb + SM_B + s * AB_BYTES);
#pragma unroll
                        for (int j = 0; j < 4; j++)   // K=16 fp16 = 32B = 2 desc units per step
                            mma_f16_ss_cg2(dbuf, ad + 2 * j, bd + 2 * j, IDESC_F16_CG2, (kc | j) != 0);
                        TCGEN05_COMMIT_MC_CG2(sb + SM_DONE + 16 * s, 0xF);   // all 4 CTAs' done
                    }
                    TCGEN05_COMMIT_MC_CG2(sb + SM_FINB + 16 * b, pmask);
                }
            }
        } else {
            // ===== forwarder (ranks 1, 3): own B ready -> arrive pair-leader's full =====
            if (elect_one_pred()) {
                int fph[STG] = {0, 0, 0, 0};
                const int gend = nt * NK;
                for (int g = 0; g < gend; g++) {
                    const int s = g & (STG - 1);
                    MBARRIER_WAIT_PARITY_RELAXED(sb + SM_FULL + 16 * s, fph[s]); fph[s] ^= 1;
                    MBARRIER_ARRIVE_LEADER(sb + SM_FULL + 16 * s);
                }
            }
        }
    } else {
        // ===== epilogue (warps 0-3 ONLY, all CTAs) =====
        const float4* b2v = (const float4*)b2;
        int finph[2] = {0, 0};
        for (int ti = 0; ti < nt; ti++) {
            const int b = ti & 1;
            MBARRIER_WAIT_PARITY(sb + SM_FINB + 16 * b, finph[b]); finph[b] ^= 1;
            TCGEN05_FENCE_AFTER();
            const int q = first + ti;
            const int nn = q & 7, mtq = q >> 3;
            const int mt = mtq * 2 + pair;
            const int row = mt * 256 + half * 128 + wid * 32 + lid;
            float4* orow = (float4*)(out + (size_t)row * VOCAB + nn * 256);
            const uint32_t dbuf = tmem + b * 256;
#pragma unroll 1
            for (int ch = 0; ch < 8; ch++) {
                uint32_t r[32];
                TCGEN05_LD_X32(r, dbuf + ch * 32);
                TCGEN05_WAIT_LD();
#pragma unroll
                for (int j = 0; j < 8; j++) {
                    float4 bb = b2v[nn * 64 + ch * 8 + j];
                    float4 v;
                    v.x = __uint_as_float(r[j * 4 + 0]) + bb.x;
                    v.y = __uint_as_float(r[j * 4 + 1]) + bb.y;
                    v.z = __uint_as_float(r[j * 4 + 2]) + bb.z;
                    v.w = __uint_as_float(r[j * 4 + 3]) + bb.w;
                    orow[ch * 8 + j] = v;
                }
            }
            TCGEN05_FENCE_BEFORE();
            asm volatile("bar.sync 1, 128;" ::: "memory");   // exactly warps 0-3
            if (tid == 0) MBARRIER_ARRIVE_LEADER(sb + SM_FREE + 16 * b);
        }
    }

    __syncthreads();
    if (wid == 0) TCGEN05_DEALLOC_CG2(tmem, 512);
    CLUSTER_SYNC();
#else
    // SIMT fallback (non-'a' target only): correct, never selected on GB300.
    (void)tma_h; (void)tma_w;
    const int rank = blockIdx.x & 3;
    for (int ti = 0; ti < nt; ti++) {
        const int q = first + ti;
        const int nn = q & 7, mtq = q >> 3;
        const int mt = mtq * 2 + (rank >> 1);
        for (int e = tid; e < 128 * 256; e += THREADS) {
            const int r = e >> 8, c = e & 255;
            const int row = mt * 256 + (rank & 1) * 128 + r;
            const __half* Ar = &g_H[(size_t)row * INNER];
            const __half* Br = &g_W2r[(size_t)(nn * 256 + c) * INNER];
            float acc = 0.f;
            for (int k = 0; k < INNER; k++) acc += __half2float(Ar[k]) * __half2float(Br[k]);
            out[(size_t)row * VOCAB + nn * 256 + c] = acc + b2[nn * 256 + c];
        }
    }
#endif
}

// ============ host ============
typedef CUresult (*PFN_encodeTiled)(
    CUtensorMap*, CUtensorMapDataType, cuuint32_t, void*,
    const cuuint64_t*, const cuuint64_t*, const cuuint32_t*, const cuuint32_t*,
    CUtensorMapInterleave, CUtensorMapSwizzle, CUtensorMapL2promotion, CUtensorMapFloatOOBfill);

static void make_map_f16(PFN_encodeTiled fn, CUtensorMap* m, void* ptr,
                         uint64_t d0, uint64_t d1, uint32_t b0, uint32_t b1) {
    cuuint64_t dims[2] = {d0, d1};
    cuuint64_t strides[1] = {d0 * 2};
    cuuint32_t box[2] = {b0, b1};
    cuuint32_t es[2] = {1, 1};
    fn(m, CU_TENSOR_MAP_DATA_TYPE_FLOAT16, 2, ptr, dims, strides, box, es,
       CU_TENSOR_MAP_INTERLEAVE_NONE, CU_TENSOR_MAP_SWIZZLE_128B,
       CU_TENSOR_MAP_L2_PROMOTION_L2_128B, CU_TENSOR_MAP_FLOAT_OOB_FILL_NONE);
}

extern "C" void kernel_launch(void* const* d_in, const int* in_sizes, int n_in,
                              void* d_out, int out_size) {
    const float* enc = (const float*)d_in[0];
    const float* dec = (const float*)d_in[1];
    const float* W1  = (const float*)d_in[2];
    const float* b1  = (const float*)d_in[3];
    const float* W2  = (const float*)d_in[4];
    const float* b2  = (const float*)d_in[5];
    float* out = (float*)d_out;

    void* hptr = nullptr; cudaGetSymbolAddress(&hptr, g_H);
    void* wptr = nullptr; cudaGetSymbolAddress(&wptr, g_W2r);

    PFN_encodeTiled enc_fn = nullptr;
    cudaDriverEntryPointQueryResult st;
    cudaGetDriverEntryPointByVersion("cuTensorMapEncodeTiled", (void**)&enc_fn, 12050,
                                     cudaEnableDefault, &st);
    CUtensorMap mapH, mapW;
    make_map_f16(enc_fn, &mapH, hptr, INNER, MROWS, KC, 128);
    make_map_f16(enc_fn, &mapW, wptr, INNER, VOCAB, KC, 128);

    cudaFuncSetAttribute(joint_gemm, cudaFuncAttributeMaxDynamicSharedMemorySize, SMEM_SZ);

    round_w2_kernel<<<VOCAB * INNER / 512, 256>>>(W2);
    proj_kernel<<<dim3(8, 20), 256>>>(enc, dec, W1, b1);
    h_kernel<<<BT, 256>>>();
    joint_gemm<<<NCLUST * 4, THREADS, SMEM_SZ>>>(mapH, mapW, b2, out);
}